// round 1
// baseline (speedup 1.0000x reference)
#include <cuda_runtime.h>
#include <mma.h>
#include <cstdint>

using namespace nvcuda;

// ---------------- problem constants ----------------
constexpr int D_MODEL = 1024;
constexpr int N_HEADS = 16;
constexpr int D_KH    = 64;     // per-head dim
constexpr int D_FF    = 4096;
constexpr int BATCH   = 4;
constexpr int SEQ     = 2048;
constexpr int TOK     = BATCH * SEQ;   // 8192

// ---------------- scratch (no allocations allowed) ----------------
__device__ float g_h  [(size_t)TOK * D_MODEL];
__device__ float g_q  [(size_t)TOK * D_MODEL];
__device__ float g_k  [(size_t)TOK * D_MODEL];
__device__ float g_v  [(size_t)TOK * D_MODEL];
__device__ float g_ctx[(size_t)TOK * D_MODEL];
__device__ float g_x1 [(size_t)TOK * D_MODEL];
__device__ float g_f1 [(size_t)TOK * D_FF];

// ============================================================
// LayerNorm (torch semantics: var ddof=1, y = a*(x-mean)/(std+eps)+b)
// one block per row, 256 threads, D=1024 -> one float4 per thread
// ============================================================
__global__ void __launch_bounds__(256) ln_kernel(
    const float* __restrict__ x, const float* __restrict__ ga,
    const float* __restrict__ gb, float* __restrict__ y)
{
    int row = blockIdx.x;
    const float4 v = ((const float4*)(x + (size_t)row * D_MODEL))[threadIdx.x];

    __shared__ float red[32];
    int lane = threadIdx.x & 31, wid = threadIdx.x >> 5;

    float s = v.x + v.y + v.z + v.w;
    #pragma unroll
    for (int o = 16; o; o >>= 1) s += __shfl_down_sync(0xffffffffu, s, o);
    if (lane == 0) red[wid] = s;
    __syncthreads();
    if (wid == 0) {
        float t = (lane < 8) ? red[lane] : 0.f;
        #pragma unroll
        for (int o = 4; o; o >>= 1) t += __shfl_down_sync(0xffffffffu, t, o);
        if (lane == 0) red[0] = t;
    }
    __syncthreads();
    float mean = red[0] * (1.f / 1024.f);

    float dx = v.x - mean, dy = v.y - mean, dz = v.z - mean, dw = v.w - mean;
    float s2 = dx*dx + dy*dy + dz*dz + dw*dw;
    #pragma unroll
    for (int o = 16; o; o >>= 1) s2 += __shfl_down_sync(0xffffffffu, s2, o);
    __syncthreads();               // everyone has read red[0]
    if (lane == 0) red[wid] = s2;
    __syncthreads();
    if (wid == 0) {
        float t = (lane < 8) ? red[lane] : 0.f;
        #pragma unroll
        for (int o = 4; o; o >>= 1) t += __shfl_down_sync(0xffffffffu, t, o);
        if (lane == 0) red[0] = t;
    }
    __syncthreads();
    float var = red[0] * (1.f / 1023.f);
    float inv = 1.f / (sqrtf(var) + 1e-5f);
    float a = ga[0] * inv, b0 = gb[0];

    float4 o4 = make_float4(a*dx + b0, a*dy + b0, a*dz + b0, a*dw + b0);
    ((float4*)(y + (size_t)row * D_MODEL))[threadIdx.x] = o4;
}

// ============================================================
// tf32 GEMM: C[M,N] = A[M,K] * W[N,K]^T + bias (+relu | +residual)
// block tile 128x64, BK=32, 256 threads (8 warps, warp tile 32x32)
// double-buffered smem; epilogue via smem staging
// EPI: 0 = bias, 1 = bias+relu, 2 = bias+residual
// ============================================================
template<int EPI>
__global__ void __launch_bounds__(256) gemm_tf32(
    const float* __restrict__ A, const float* __restrict__ W,
    const float* __restrict__ bias, const float* __restrict__ resid,
    float* __restrict__ C, int M, int N, int K)
{
    constexpr int BM = 128, BN = 64, BK = 32, LDS = 36;
    extern __shared__ float sm[];
    float* As = sm;                       // 2 * BM*LDS
    float* Bs = sm + 2 * BM * LDS;        // 2 * BN*LDS

    const int tid = threadIdx.x;
    const int m0 = blockIdx.y * BM, n0 = blockIdx.x * BN;
    const int KT = K / BK;

    float4 ra[4], rb[2];

    auto loadA = [&](int kt) {
        #pragma unroll
        for (int i = 0; i < 4; i++) {
            int lin = i * 256 + tid, r = lin >> 3, c = lin & 7;
            ra[i] = *(const float4*)(A + (size_t)(m0 + r) * K + kt * BK + c * 4);
        }
    };
    auto loadB = [&](int kt) {
        #pragma unroll
        for (int i = 0; i < 2; i++) {
            int lin = i * 256 + tid, r = lin >> 3, c = lin & 7;
            rb[i] = *(const float4*)(W + (size_t)(n0 + r) * K + kt * BK + c * 4);
        }
    };
    auto storeS = [&](int buf) {
        float* Ab = As + buf * BM * LDS;
        float* Bb = Bs + buf * BN * LDS;
        #pragma unroll
        for (int i = 0; i < 4; i++) {
            int lin = i * 256 + tid, r = lin >> 3, c = lin & 7;
            *(float4*)(Ab + r * LDS + c * 4) = ra[i];
        }
        #pragma unroll
        for (int i = 0; i < 2; i++) {
            int lin = i * 256 + tid, r = lin >> 3, c = lin & 7;
            *(float4*)(Bb + r * LDS + c * 4) = rb[i];
        }
    };

    const int warp = tid >> 5, wm = warp >> 1, wn = warp & 1;

    wmma::fragment<wmma::accumulator, 16, 16, 8, float> cf[2][2];
    #pragma unroll
    for (int i = 0; i < 2; i++)
        #pragma unroll
        for (int j = 0; j < 2; j++) wmma::fill_fragment(cf[i][j], 0.f);

    loadA(0); loadB(0);
    int buf = 0;
    for (int kt = 0; kt < KT; kt++) {
        storeS(buf);
        __syncthreads();
        if (kt + 1 < KT) { loadA(kt + 1); loadB(kt + 1); }

        const float* Ab = As + buf * BM * LDS + (wm * 32) * LDS;
        const float* Bb = Bs + buf * BN * LDS + (wn * 32) * LDS;
        #pragma unroll
        for (int kk = 0; kk < 4; kk++) {
            wmma::fragment<wmma::matrix_a, 16, 16, 8, wmma::precision::tf32, wmma::row_major> af[2];
            wmma::fragment<wmma::matrix_b, 16, 16, 8, wmma::precision::tf32, wmma::col_major> bf[2];
            #pragma unroll
            for (int mi = 0; mi < 2; mi++) {
                wmma::load_matrix_sync(af[mi], Ab + (mi * 16) * LDS + kk * 8, LDS);
                #pragma unroll
                for (int t = 0; t < af[mi].num_elements; t++)
                    af[mi].x[t] = wmma::__float_to_tf32(af[mi].x[t]);
            }
            #pragma unroll
            for (int nj = 0; nj < 2; nj++) {
                wmma::load_matrix_sync(bf[nj], Bb + (nj * 16) * LDS + kk * 8, LDS);
                #pragma unroll
                for (int t = 0; t < bf[nj].num_elements; t++)
                    bf[nj].x[t] = wmma::__float_to_tf32(bf[nj].x[t]);
            }
            #pragma unroll
            for (int mi = 0; mi < 2; mi++)
                #pragma unroll
                for (int nj = 0; nj < 2; nj++)
                    wmma::mma_sync(cf[mi][nj], af[mi], bf[nj], cf[mi][nj]);
        }
        buf ^= 1;
        __syncthreads();
    }

    // epilogue: stage to smem (reuse), then bias/relu/residual + store
    float* Cs = sm;  // 128 * 68 floats fits
    #pragma unroll
    for (int mi = 0; mi < 2; mi++)
        #pragma unroll
        for (int nj = 0; nj < 2; nj++)
            wmma::store_matrix_sync(Cs + (wm*32 + mi*16) * 68 + wn*32 + nj*16,
                                    cf[mi][nj], 68, wmma::mem_row_major);
    __syncthreads();
    #pragma unroll
    for (int i = 0; i < 8; i++) {
        int lin = i * 256 + tid, r = lin >> 4, c4 = lin & 15;
        float4 v = *(float4*)(Cs + r * 68 + c4 * 4);
        float4 bv = *(const float4*)(bias + n0 + c4 * 4);
        v.x += bv.x; v.y += bv.y; v.z += bv.z; v.w += bv.w;
        if (EPI == 1) {
            v.x = fmaxf(v.x, 0.f); v.y = fmaxf(v.y, 0.f);
            v.z = fmaxf(v.z, 0.f); v.w = fmaxf(v.w, 0.f);
        }
        if (EPI == 2) {
            float4 rv = *(const float4*)(resid + (size_t)(m0 + r) * N + n0 + c4 * 4);
            v.x += rv.x; v.y += rv.y; v.z += rv.z; v.w += rv.w;
        }
        *(float4*)(C + (size_t)(m0 + r) * N + n0 + c4 * 4) = v;
    }
}

// ============================================================
// Flash attention, tf32 wmma, fp32 softmax.
// grid = (SEQ/64, BATCH*N_HEADS), 128 threads (4 warps).
// Q/K/V/ctx layout: [token, head*64+d] with row stride D_MODEL.
// ============================================================
__global__ void __launch_bounds__(128) attn_kernel(
    const float* __restrict__ Q, const float* __restrict__ K,
    const float* __restrict__ V, float* __restrict__ O)
{
    constexpr int LD = 68;
    extern __shared__ float sm[];
    float* Qs = sm;
    float* Ks = Qs + 64 * LD;
    float* Vs = Ks + 64 * LD;
    float* Ss = Vs + 64 * LD;
    float* Os = Ss + 64 * LD;
    float* Ml = Os + 64 * LD;
    float* Ll = Ml + 64;

    const int tid = threadIdx.x;
    const int b = blockIdx.y >> 4, h = blockIdx.y & 15;
    const size_t base = (size_t)b * SEQ * D_MODEL + (size_t)h * 64;
    const int q0 = blockIdx.x * 64;

    // load Q (scaled by 1/sqrt(64) = 0.125), init O, m, l
    #pragma unroll
    for (int i = 0; i < 8; i++) {
        int lin = i * 128 + tid, r = lin >> 4, c4 = lin & 15;
        float4 v = *(const float4*)(Q + base + (size_t)(q0 + r) * D_MODEL + c4 * 4);
        v.x *= 0.125f; v.y *= 0.125f; v.z *= 0.125f; v.w *= 0.125f;
        *(float4*)(Qs + r * LD + c4 * 4) = v;
        *(float4*)(Os + r * LD + c4 * 4) = make_float4(0.f, 0.f, 0.f, 0.f);
    }
    if (tid < 64) { Ml[tid] = -1e30f; Ll[tid] = 0.f; }
    __syncthreads();

    const int w = tid >> 5;

    for (int kt = 0; kt < SEQ / 64; kt++) {
        const int k0 = kt * 64;
        // load K,V tiles
        #pragma unroll
        for (int i = 0; i < 8; i++) {
            int lin = i * 128 + tid, r = lin >> 4, c4 = lin & 15;
            *(float4*)(Ks + r * LD + c4 * 4) =
                *(const float4*)(K + base + (size_t)(k0 + r) * D_MODEL + c4 * 4);
            *(float4*)(Vs + r * LD + c4 * 4) =
                *(const float4*)(V + base + (size_t)(k0 + r) * D_MODEL + c4 * 4);
        }
        __syncthreads();

        // S = Qs * Ks^T   (each warp: 16 query rows x 64 key cols)
        {
            wmma::fragment<wmma::accumulator, 16, 16, 8, float> sf[4];
            #pragma unroll
            for (int nj = 0; nj < 4; nj++) wmma::fill_fragment(sf[nj], 0.f);
            #pragma unroll
            for (int kk = 0; kk < 8; kk++) {
                wmma::fragment<wmma::matrix_a, 16, 16, 8, wmma::precision::tf32, wmma::row_major> af;
                wmma::load_matrix_sync(af, Qs + (w * 16) * LD + kk * 8, LD);
                #pragma unroll
                for (int t = 0; t < af.num_elements; t++)
                    af.x[t] = wmma::__float_to_tf32(af.x[t]);
                #pragma unroll
                for (int nj = 0; nj < 4; nj++) {
                    wmma::fragment<wmma::matrix_b, 16, 16, 8, wmma::precision::tf32, wmma::col_major> bf;
                    wmma::load_matrix_sync(bf, Ks + (nj * 16) * LD + kk * 8, LD);
                    #pragma unroll
                    for (int t = 0; t < bf.num_elements; t++)
                        bf.x[t] = wmma::__float_to_tf32(bf.x[t]);
                    wmma::mma_sync(sf[nj], af, bf, sf[nj]);
                }
            }
            #pragma unroll
            for (int nj = 0; nj < 4; nj++)
                wmma::store_matrix_sync(Ss + (w * 16) * LD + nj * 16, sf[nj], LD,
                                        wmma::mem_row_major);
        }
        __syncthreads();

        // online softmax: 2 threads per row, 32 cols each
        {
            const int row = tid >> 1, half = tid & 1;
            float* sr = Ss + row * LD + half * 32;
            float mx = -1e30f;
            #pragma unroll 8
            for (int c = 0; c < 32; c++) mx = fmaxf(mx, sr[c]);
            mx = fmaxf(mx, __shfl_xor_sync(0xffffffffu, mx, 1));
            const float mold = Ml[row];
            const float mnew = fmaxf(mold, mx);
            const float fac = __expf(mold - mnew);
            float ssum = 0.f;
            #pragma unroll 8
            for (int c = 0; c < 32; c++) {
                float e = __expf(sr[c] - mnew);
                sr[c] = e;
                ssum += e;
            }
            ssum += __shfl_xor_sync(0xffffffffu, ssum, 1);
            float* orow = Os + row * LD + half * 32;
            #pragma unroll 8
            for (int c = 0; c < 32; c++) orow[c] *= fac;
            if (half == 0) { Ml[row] = mnew; Ll[row] = Ll[row] * fac + ssum; }
        }
        __syncthreads();

        // O += P * V
        {
            #pragma unroll
            for (int nj = 0; nj < 4; nj++) {
                wmma::fragment<wmma::accumulator, 16, 16, 8, float> of;
                wmma::load_matrix_sync(of, Os + (w * 16) * LD + nj * 16, LD,
                                       wmma::mem_row_major);
                #pragma unroll
                for (int kk = 0; kk < 8; kk++) {
                    wmma::fragment<wmma::matrix_a, 16, 16, 8, wmma::precision::tf32, wmma::row_major> af;
                    wmma::load_matrix_sync(af, Ss + (w * 16) * LD + kk * 8, LD);
                    #pragma unroll
                    for (int t = 0; t < af.num_elements; t++)
                        af.x[t] = wmma::__float_to_tf32(af.x[t]);
                    wmma::fragment<wmma::matrix_b, 16, 16, 8, wmma::precision::tf32, wmma::row_major> bf;
                    wmma::load_matrix_sync(bf, Vs + (kk * 8) * LD + nj * 16, LD);
                    #pragma unroll
                    for (int t = 0; t < bf.num_elements; t++)
                        bf.x[t] = wmma::__float_to_tf32(bf.x[t]);
                    wmma::mma_sync(of, af, bf, of);
                }
                wmma::store_matrix_sync(Os + (w * 16) * LD + nj * 16, of, LD,
                                        wmma::mem_row_major);
            }
        }
        __syncthreads();
    }

    // normalize + store
    {
        const int row = tid >> 1, half = tid & 1;
        const float invl = 1.f / Ll[row];
        #pragma unroll
        for (int c4 = 0; c4 < 8; c4++) {
            float4 v = *(float4*)(Os + row * LD + half * 32 + c4 * 4);
            v.x *= invl; v.y *= invl; v.z *= invl; v.w *= invl;
            *(float4*)(O + base + (size_t)(q0 + row) * D_MODEL + half * 32 + c4 * 4) = v;
        }
    }
}

// ============================================================
// launcher
// ============================================================
extern "C" void kernel_launch(void* const* d_in, const int* in_sizes, int n_in,
                              void* d_out, int out_size)
{
    const float* x     = (const float*)d_in[0];
    // d_in[1] = mask (all true; reference broadcast (1,1,1,S) of ones) — unused
    const float* wq    = (const float*)d_in[2];
    const float* bq    = (const float*)d_in[3];
    const float* wk    = (const float*)d_in[4];
    const float* bk    = (const float*)d_in[5];
    const float* wv    = (const float*)d_in[6];
    const float* bv    = (const float*)d_in[7];
    const float* wo    = (const float*)d_in[8];
    const float* bo    = (const float*)d_in[9];
    const float* w1    = (const float*)d_in[10];
    const float* b1    = (const float*)d_in[11];
    const float* w2    = (const float*)d_in[12];
    const float* b2    = (const float*)d_in[13];
    const float* ln1a  = (const float*)d_in[14];
    const float* ln1b  = (const float*)d_in[15];
    const float* ln2a  = (const float*)d_in[16];
    const float* ln2b  = (const float*)d_in[17];
    float* out = (float*)d_out;

    void* p;
    cudaGetSymbolAddress(&p, g_h);   float* h   = (float*)p;
    cudaGetSymbolAddress(&p, g_q);   float* q   = (float*)p;
    cudaGetSymbolAddress(&p, g_k);   float* k   = (float*)p;
    cudaGetSymbolAddress(&p, g_v);   float* v   = (float*)p;
    cudaGetSymbolAddress(&p, g_ctx); float* ctx = (float*)p;
    cudaGetSymbolAddress(&p, g_x1);  float* x1  = (float*)p;
    cudaGetSymbolAddress(&p, g_f1);  float* f1  = (float*)p;

    constexpr int SMEM_G = 2 * (128 + 64) * 36 * 4;      // 55296 B
    constexpr int SMEM_A = (5 * 64 * 68 + 128) * 4;      // 87552 B
    cudaFuncSetAttribute(gemm_tf32<0>, cudaFuncAttributeMaxDynamicSharedMemorySize, SMEM_G);
    cudaFuncSetAttribute(gemm_tf32<1>, cudaFuncAttributeMaxDynamicSharedMemorySize, SMEM_G);
    cudaFuncSetAttribute(gemm_tf32<2>, cudaFuncAttributeMaxDynamicSharedMemorySize, SMEM_G);
    cudaFuncSetAttribute(attn_kernel, cudaFuncAttributeMaxDynamicSharedMemorySize, SMEM_A);

    // 1) LN1
    ln_kernel<<<TOK, 256>>>(x, ln1a, ln1b, h);

    // 2) Q,K,V projections
    dim3 gqkv(D_MODEL / 64, TOK / 128);
    gemm_tf32<0><<<gqkv, 256, SMEM_G>>>(h, wq, bq, nullptr, q, TOK, D_MODEL, D_MODEL);
    gemm_tf32<0><<<gqkv, 256, SMEM_G>>>(h, wk, bk, nullptr, k, TOK, D_MODEL, D_MODEL);
    gemm_tf32<0><<<gqkv, 256, SMEM_G>>>(h, wv, bv, nullptr, v, TOK, D_MODEL, D_MODEL);

    // 3) flash attention
    attn_kernel<<<dim3(SEQ / 64, BATCH * N_HEADS), 128, SMEM_A>>>(q, k, v, ctx);

    // 4) output projection + residual 1
    gemm_tf32<2><<<gqkv, 256, SMEM_G>>>(ctx, wo, bo, x, x1, TOK, D_MODEL, D_MODEL);

    // 5) LN2
    ln_kernel<<<TOK, 256>>>(x1, ln2a, ln2b, h);

    // 6) FFN
    gemm_tf32<1><<<dim3(D_FF / 64, TOK / 128), 256, SMEM_G>>>(h, w1, b1, nullptr, f1, TOK, D_FF, D_MODEL);
    gemm_tf32<2><<<gqkv, 256, SMEM_G>>>(f1, w2, b2, x1, out, TOK, D_MODEL, D_FF);
}

// round 8
// speedup vs baseline: 2.9528x; 2.9528x over previous
#include <cuda_runtime.h>
#include <cuda_fp16.h>
#include <mma.h>
#include <cstdint>

using namespace nvcuda;

// ---------------- problem constants ----------------
constexpr int D_MODEL = 1024;
constexpr int N_HEADS = 16;
constexpr int D_FF    = 4096;
constexpr int BATCH   = 4;
constexpr int SEQ     = 2048;
constexpr int TOK     = BATCH * SEQ;   // 8192

// ---------------- scratch (device globals; no allocation allowed) ----------------
__device__ __half g_h  [(size_t)TOK * D_MODEL];
__device__ __half g_q  [(size_t)TOK * D_MODEL];
__device__ __half g_k  [(size_t)TOK * D_MODEL];
__device__ __half g_v  [(size_t)TOK * D_MODEL];
__device__ __half g_ctx[(size_t)TOK * D_MODEL];
__device__ __half g_f1 [(size_t)TOK * D_FF];
__device__ float  g_x1 [(size_t)TOK * D_MODEL];
__device__ __half g_wq [(size_t)D_MODEL * D_MODEL];
__device__ __half g_wk [(size_t)D_MODEL * D_MODEL];
__device__ __half g_wv [(size_t)D_MODEL * D_MODEL];
__device__ __half g_wo [(size_t)D_MODEL * D_MODEL];
__device__ __half g_w1 [(size_t)D_FF * D_MODEL];
__device__ __half g_w2 [(size_t)D_MODEL * D_FF];

// ================= cp.async =================
#define CP_ASYNC16(dst, src) \
    asm volatile("cp.async.cg.shared.global [%0], [%1], 16;" :: "r"(dst), "l"(src))
#define CP_COMMIT() asm volatile("cp.async.commit_group;")
#define CP_WAIT2()  asm volatile("cp.async.wait_group 2;")

__device__ __forceinline__ uint32_t smem_u32(const void* p) {
    uint32_t a;
    asm("{ .reg .u64 t; cvta.to.shared.u64 t, %1; cvt.u32.u64 %0, t; }" : "=r"(a) : "l"(p));
    return a;
}

// ============================================================
// weight fp32 -> fp16 conversion
// ============================================================
__global__ void __launch_bounds__(256) f2h_kernel(const float* __restrict__ s,
                                                  __half* __restrict__ d, int n) {
    int i = (blockIdx.x * 256 + threadIdx.x) * 4;
    if (i < n) {
        float4 v = *(const float4*)(s + i);
        union { __half2 h[2]; uint2 u; } c;
        c.h[0] = __floats2half2_rn(v.x, v.y);
        c.h[1] = __floats2half2_rn(v.z, v.w);
        *(uint2*)(d + i) = c.u;
    }
}

// ============================================================
// LayerNorm (torch semantics: ddof=1, /(std+eps)) fp32 in -> fp16 out
// ============================================================
__global__ void __launch_bounds__(256) ln_kernel(
    const float* __restrict__ x, const float* __restrict__ ga,
    const float* __restrict__ gb, __half* __restrict__ y)
{
    int row = blockIdx.x;
    const float4 v = ((const float4*)(x + (size_t)row * D_MODEL))[threadIdx.x];

    __shared__ float red[32];
    int lane = threadIdx.x & 31, wid = threadIdx.x >> 5;

    float s = v.x + v.y + v.z + v.w;
    #pragma unroll
    for (int o = 16; o; o >>= 1) s += __shfl_down_sync(0xffffffffu, s, o);
    if (lane == 0) red[wid] = s;
    __syncthreads();
    if (wid == 0) {
        float t = (lane < 8) ? red[lane] : 0.f;
        #pragma unroll
        for (int o = 4; o; o >>= 1) t += __shfl_down_sync(0xffffffffu, t, o);
        if (lane == 0) red[0] = t;
    }
    __syncthreads();
    float mean = red[0] * (1.f / 1024.f);

    float dx = v.x - mean, dy = v.y - mean, dz = v.z - mean, dw = v.w - mean;
    float s2 = dx*dx + dy*dy + dz*dz + dw*dw;
    #pragma unroll
    for (int o = 16; o; o >>= 1) s2 += __shfl_down_sync(0xffffffffu, s2, o);
    __syncthreads();
    if (lane == 0) red[wid] = s2;
    __syncthreads();
    if (wid == 0) {
        float t = (lane < 8) ? red[lane] : 0.f;
        #pragma unroll
        for (int o = 4; o; o >>= 1) t += __shfl_down_sync(0xffffffffu, t, o);
        if (lane == 0) red[0] = t;
    }
    __syncthreads();
    float var = red[0] * (1.f / 1023.f);
    float inv = 1.f / (sqrtf(var) + 1e-5f);
    float a = ga[0] * inv, b0 = gb[0];

    union { __half2 h[2]; uint2 u; } c;
    c.h[0] = __floats2half2_rn(a*dx + b0, a*dy + b0);
    c.h[1] = __floats2half2_rn(a*dz + b0, a*dw + b0);
    ((uint2*)(y + (size_t)row * D_MODEL))[threadIdx.x] = c.u;
}

// ============================================================
// fp16 HMMA GEMM: C[M,N] = A[M,K] * W[N,K]^T + bias ...
// CTA tile 128x128, BK=64, 3-stage cp.async pipeline, 256 threads.
// 8 warps, warp tile 32x64 (2x4 frags of 16x16x16).
// EPI: 0 = fp16 out (+bias), 1 = fp16 out (+bias,relu), 2 = fp32 out (+bias,+resid)
// ============================================================
constexpr int BM = 128, BN = 128, BK = 64;
constexpr int LDS = 72;                       // halves, +8 pad
constexpr int TILE_HALVES = 128 * LDS;        // per operand per stage
constexpr int STAGE_BYTES = 2 * TILE_HALVES * 2;          // A+B = 36864
constexpr int G_STAGES = 3;
constexpr int G_SMEM = G_STAGES * STAGE_BYTES;            // 110592

template<int EPI>
__global__ void __launch_bounds__(256) gemm_h(
    const __half* __restrict__ A, const __half* __restrict__ W,
    const float* __restrict__ bias, const float* __restrict__ resid,
    float* __restrict__ Cf, __half* __restrict__ Ch, int N, int K)
{
    extern __shared__ __align__(16) char smraw[];
    __half* sm = (__half*)smraw;
    const uint32_t smb = smem_u32(sm);

    const int tid = threadIdx.x;
    const int m0 = blockIdx.y * BM, n0 = blockIdx.x * BN;
    const int KT = K >> 6;

    auto fill = [&](int kb) {
        const int st = kb % G_STAGES;
        const uint32_t sA = smb + st * STAGE_BYTES;
        const uint32_t sB = sA + TILE_HALVES * 2;
        const __half* gA = A + (size_t)m0 * K + kb * BK;
        const __half* gB = W + (size_t)n0 * K + kb * BK;
        #pragma unroll
        for (int i = 0; i < 4; i++) {
            int lin = i * 256 + tid, r = lin >> 3, c = lin & 7;
            CP_ASYNC16(sA + r * (LDS * 2) + c * 16, gA + (size_t)r * K + c * 8);
        }
        #pragma unroll
        for (int i = 0; i < 4; i++) {
            int lin = i * 256 + tid, r = lin >> 3, c = lin & 7;
            CP_ASYNC16(sB + r * (LDS * 2) + c * 16, gB + (size_t)r * K + c * 8);
        }
        CP_COMMIT();
    };

    const int warp = tid >> 5, wm = warp >> 1, wn = warp & 1;

    wmma::fragment<wmma::accumulator, 16, 16, 16, float> cf[2][4];
    #pragma unroll
    for (int i = 0; i < 2; i++)
        #pragma unroll
        for (int j = 0; j < 4; j++) wmma::fill_fragment(cf[i][j], 0.f);

    fill(0); fill(1); fill(2);

    for (int kb = 0; kb < KT; kb++) {
        const int st = kb % G_STAGES;
        CP_WAIT2();
        __syncthreads();

        const __half* As = sm + st * (STAGE_BYTES / 2) + (wm * 32) * LDS;
        const __half* Bs = sm + st * (STAGE_BYTES / 2) + TILE_HALVES + (wn * 64) * LDS;

        #pragma unroll
        for (int kk = 0; kk < 4; kk++) {
            wmma::fragment<wmma::matrix_a, 16, 16, 16, __half, wmma::row_major> af[2];
            #pragma unroll
            for (int mi = 0; mi < 2; mi++)
                wmma::load_matrix_sync(af[mi], As + (mi * 16) * LDS + kk * 16, LDS);
            #pragma unroll
            for (int nj = 0; nj < 4; nj++) {
                wmma::fragment<wmma::matrix_b, 16, 16, 16, __half, wmma::col_major> bf;
                wmma::load_matrix_sync(bf, Bs + (nj * 16) * LDS + kk * 16, LDS);
                #pragma unroll
                for (int mi = 0; mi < 2; mi++)
                    wmma::mma_sync(cf[mi][nj], af[mi], bf, cf[mi][nj]);
            }
        }
        __syncthreads();
        if (kb + G_STAGES < KT) fill(kb + G_STAGES); else CP_COMMIT();
    }

    // epilogue: stage accum to smem (reuse pipeline smem), then fused store
    float* Cs = (float*)sm;                    // 128 x 136 floats = 69632 B < G_SMEM
    constexpr int LDC = 136;
    #pragma unroll
    for (int mi = 0; mi < 2; mi++)
        #pragma unroll
        for (int nj = 0; nj < 4; nj++)
            wmma::store_matrix_sync(Cs + (wm*32 + mi*16) * LDC + wn*64 + nj*16,
                                    cf[mi][nj], LDC, wmma::mem_row_major);
    __syncthreads();

    #pragma unroll
    for (int i = 0; i < 16; i++) {
        int lin = i * 256 + tid, r = lin >> 5, c4 = lin & 31;
        float4 v = *(float4*)(Cs + r * LDC + c4 * 4);
        float4 bv = *(const float4*)(bias + n0 + c4 * 4);
        v.x += bv.x; v.y += bv.y; v.z += bv.z; v.w += bv.w;
        if (EPI == 1) {
            v.x = fmaxf(v.x, 0.f); v.y = fmaxf(v.y, 0.f);
            v.z = fmaxf(v.z, 0.f); v.w = fmaxf(v.w, 0.f);
        }
        if (EPI == 2) {
            float4 rv = *(const float4*)(resid + (size_t)(m0 + r) * N + n0 + c4 * 4);
            v.x += rv.x; v.y += rv.y; v.z += rv.z; v.w += rv.w;
            *(float4*)(Cf + (size_t)(m0 + r) * N + n0 + c4 * 4) = v;
        } else {
            union { __half2 h[2]; uint2 u; } stv;
            stv.h[0] = __floats2half2_rn(v.x, v.y);
            stv.h[1] = __floats2half2_rn(v.z, v.w);
            *(uint2*)(Ch + (size_t)(m0 + r) * N + n0 + c4 * 4) = stv.u;
        }
    }
}

// ============================================================
// Flash attention, fp16 wmma (m16n16k16), fp32 softmax/accum.
// grid = (SEQ/64, BATCH*N_HEADS), 128 threads (4 warps).
// ============================================================
constexpr int LDH = 72;   // half row stride
constexpr int LDF = 68;   // float row stride
constexpr int ATTN_SMEM = 4 * 64 * LDH * 2 + 2 * 64 * LDF * 4 + 2 * 64 * 4; // 72192

__global__ void __launch_bounds__(128) attn_kernel(
    const __half* __restrict__ Q, const __half* __restrict__ K,
    const __half* __restrict__ V, __half* __restrict__ O)
{
    extern __shared__ __align__(16) char sm[];
    __half* Qs = (__half*)(sm);
    __half* Ks = Qs + 64 * LDH;
    __half* Vs = Ks + 64 * LDH;
    __half* Ps = Vs + 64 * LDH;
    float*  Ss = (float*)(Ps + 64 * LDH);
    float*  Os = Ss + 64 * LDF;
    float*  Ml = Os + 64 * LDF;
    float*  Ll = Ml + 64;

    const int tid = threadIdx.x;
    const int b = blockIdx.y >> 4, h = blockIdx.y & 15;
    const size_t base = (size_t)b * SEQ * D_MODEL + (size_t)h * 64;
    const int q0 = blockIdx.x * 64;
    const __half2 qs2 = __floats2half2_rn(0.125f, 0.125f);

    // load Q (scaled by exact 1/8), init O/m/l
    #pragma unroll
    for (int i = 0; i < 4; i++) {
        int lin = i * 128 + tid, r = lin >> 3, c = lin & 7;
        union { __half2 h[4]; uint4 u; } v;
        v.u = *(const uint4*)(Q + base + (size_t)(q0 + r) * D_MODEL + c * 8);
        #pragma unroll
        for (int t = 0; t < 4; t++) v.h[t] = __hmul2(v.h[t], qs2);
        *(uint4*)(Qs + r * LDH + c * 8) = v.u;
    }
    #pragma unroll
    for (int i = 0; i < 8; i++) {
        int lin = i * 128 + tid, r = lin >> 4, c4 = lin & 15;
        *(float4*)(Os + r * LDF + c4 * 4) = make_float4(0.f, 0.f, 0.f, 0.f);
    }
    if (tid < 64) { Ml[tid] = -1e30f; Ll[tid] = 0.f; }
    __syncthreads();

    const int w = tid >> 5;

    for (int kt = 0; kt < SEQ / 64; kt++) {
        const int k0 = kt * 64;
        #pragma unroll
        for (int i = 0; i < 4; i++) {
            int lin = i * 128 + tid, r = lin >> 3, c = lin & 7;
            *(uint4*)(Ks + r * LDH + c * 8) =
                *(const uint4*)(K + base + (size_t)(k0 + r) * D_MODEL + c * 8);
            *(uint4*)(Vs + r * LDH + c * 8) =
                *(const uint4*)(V + base + (size_t)(k0 + r) * D_MODEL + c * 8);
        }
        __syncthreads();

        // S = Qs * Ks^T  (warp: 16 q-rows x 64 keys)
        {
            wmma::fragment<wmma::accumulator, 16, 16, 16, float> sf[4];
            #pragma unroll
            for (int nj = 0; nj < 4; nj++) wmma::fill_fragment(sf[nj], 0.f);
            #pragma unroll
            for (int kk = 0; kk < 4; kk++) {
                wmma::fragment<wmma::matrix_a, 16, 16, 16, __half, wmma::row_major> af;
                wmma::load_matrix_sync(af, Qs + (w * 16) * LDH + kk * 16, LDH);
                #pragma unroll
                for (int nj = 0; nj < 4; nj++) {
                    wmma::fragment<wmma::matrix_b, 16, 16, 16, __half, wmma::col_major> bf;
                    wmma::load_matrix_sync(bf, Ks + (nj * 16) * LDH + kk * 16, LDH);
                    wmma::mma_sync(sf[nj], af, bf, sf[nj]);
                }
            }
            #pragma unroll
            for (int nj = 0; nj < 4; nj++)
                wmma::store_matrix_sync(Ss + (w * 16) * LDF + nj * 16, sf[nj], LDF,
                                        wmma::mem_row_major);
        }
        __syncthreads();

        // online softmax: 2 threads/row, write P in fp16
        {
            const int row = tid >> 1, hh = tid & 1;
            float* sr = Ss + row * LDF + hh * 32;
            __half* pr = Ps + row * LDH + hh * 32;
            float mx = -1e30f;
            #pragma unroll 8
            for (int c = 0; c < 32; c++) mx = fmaxf(mx, sr[c]);
            mx = fmaxf(mx, __shfl_xor_sync(0xffffffffu, mx, 1));
            const float mold = Ml[row];
            const float mnew = fmaxf(mold, mx);
            const float fac = __expf(mold - mnew);
            float ssum = 0.f;
            #pragma unroll 8
            for (int c = 0; c < 32; c++) {
                float e = __expf(sr[c] - mnew);
                pr[c] = __float2half(e);
                ssum += e;
            }
            ssum += __shfl_xor_sync(0xffffffffu, ssum, 1);
            float* orow = Os + row * LDF + hh * 32;
            #pragma unroll 8
            for (int c = 0; c < 32; c++) orow[c] *= fac;
            if (hh == 0) { Ml[row] = mnew; Ll[row] = Ll[row] * fac + ssum; }
        }
        __syncthreads();

        // O += P * V
        {
            #pragma unroll
            for (int nj = 0; nj < 4; nj++) {
                wmma::fragment<wmma::accumulator, 16, 16, 16, float> of;
                wmma::load_matrix_sync(of, Os + (w * 16) * LDF + nj * 16, LDF,
                                       wmma::mem_row_major);
                #pragma unroll
                for (int kk = 0; kk < 4; kk++) {
                    wmma::fragment<wmma::matrix_a, 16, 16, 16, __half, wmma::row_major> af;
                    wmma::load_matrix_sync(af, Ps + (w * 16) * LDH + kk * 16, LDH);
                    wmma::fragment<wmma::matrix_b, 16, 16, 16, __half, wmma::row_major> bf;
                    wmma::load_matrix_sync(bf, Vs + (kk * 16) * LDH + nj * 16, LDH);
                    wmma::mma_sync(of, af, bf, of);
                }
                wmma::store_matrix_sync(Os + (w * 16) * LDF + nj * 16, of, LDF,
                                        wmma::mem_row_major);
            }
        }
        __syncthreads();
    }

    // normalize + store fp16
    {
        const int row = tid >> 1, hh = tid & 1;
        const float inv = 1.f / Ll[row];
        #pragma unroll
        for (int c4 = 0; c4 < 8; c4++) {
            float4 v = *(float4*)(Os + row * LDF + hh * 32 + c4 * 4);
            union { __half2 h[2]; uint2 u; } st;
            st.h[0] = __floats2half2_rn(v.x * inv, v.y * inv);
            st.h[1] = __floats2half2_rn(v.z * inv, v.w * inv);
            *(uint2*)(O + base + (size_t)(q0 + row) * D_MODEL + hh * 32 + c4 * 4) = st.u;
        }
    }
}

// ============================================================
// launcher
// ============================================================
extern "C" void kernel_launch(void* const* d_in, const int* in_sizes, int n_in,
                              void* d_out, int out_size)
{
    const float* x    = (const float*)d_in[0];
    const float* wq   = (const float*)d_in[2];
    const float* bq   = (const float*)d_in[3];
    const float* wk   = (const float*)d_in[4];
    const float* bk   = (const float*)d_in[5];
    const float* wv   = (const float*)d_in[6];
    const float* bv   = (const float*)d_in[7];
    const float* wo   = (const float*)d_in[8];
    const float* bo   = (const float*)d_in[9];
    const float* w1   = (const float*)d_in[10];
    const float* b1   = (const float*)d_in[11];
    const float* w2   = (const float*)d_in[12];
    const float* b2   = (const float*)d_in[13];
    const float* ln1a = (const float*)d_in[14];
    const float* ln1b = (const float*)d_in[15];
    const float* ln2a = (const float*)d_in[16];
    const float* ln2b = (const float*)d_in[17];
    float* out = (float*)d_out;

    void* p;
    cudaGetSymbolAddress(&p, g_h);   __half* h   = (__half*)p;
    cudaGetSymbolAddress(&p, g_q);   __half* q   = (__half*)p;
    cudaGetSymbolAddress(&p, g_k);   __half* k   = (__half*)p;
    cudaGetSymbolAddress(&p, g_v);   __half* v   = (__half*)p;
    cudaGetSymbolAddress(&p, g_ctx); __half* ctx = (__half*)p;
    cudaGetSymbolAddress(&p, g_f1);  __half* f1  = (__half*)p;
    cudaGetSymbolAddress(&p, g_x1);  float*  x1  = (float*)p;
    cudaGetSymbolAddress(&p, g_wq);  __half* wqh = (__half*)p;
    cudaGetSymbolAddress(&p, g_wk);  __half* wkh = (__half*)p;
    cudaGetSymbolAddress(&p, g_wv);  __half* wvh = (__half*)p;
    cudaGetSymbolAddress(&p, g_wo);  __half* woh = (__half*)p;
    cudaGetSymbolAddress(&p, g_w1);  __half* w1h = (__half*)p;
    cudaGetSymbolAddress(&p, g_w2);  __half* w2h = (__half*)p;

    cudaFuncSetAttribute(gemm_h<0>, cudaFuncAttributeMaxDynamicSharedMemorySize, G_SMEM);
    cudaFuncSetAttribute(gemm_h<1>, cudaFuncAttributeMaxDynamicSharedMemorySize, G_SMEM);
    cudaFuncSetAttribute(gemm_h<2>, cudaFuncAttributeMaxDynamicSharedMemorySize, G_SMEM);
    cudaFuncSetAttribute(attn_kernel, cudaFuncAttributeMaxDynamicSharedMemorySize, ATTN_SMEM);

    // weights -> fp16
    const int NW1 = D_MODEL * D_MODEL, NW2 = D_FF * D_MODEL;
    f2h_kernel<<<NW1 / 1024, 256>>>(wq, wqh, NW1);
    f2h_kernel<<<NW1 / 1024, 256>>>(wk, wkh, NW1);
    f2h_kernel<<<NW1 / 1024, 256>>>(wv, wvh, NW1);
    f2h_kernel<<<NW1 / 1024, 256>>>(wo, woh, NW1);
    f2h_kernel<<<NW2 / 1024, 256>>>(w1, w1h, NW2);
    f2h_kernel<<<NW2 / 1024, 256>>>(w2, w2h, NW2);

    // 1) LN1 -> h (fp16)
    ln_kernel<<<TOK, 256>>>(x, ln1a, ln1b, h);

    // 2) QKV projections (fp16 out)
    dim3 g1024(D_MODEL / 128, TOK / 128);
    gemm_h<0><<<g1024, 256, G_SMEM>>>(h, wqh, bq, nullptr, nullptr, q, D_MODEL, D_MODEL);
    gemm_h<0><<<g1024, 256, G_SMEM>>>(h, wkh, bk, nullptr, nullptr, k, D_MODEL, D_MODEL);
    gemm_h<0><<<g1024, 256, G_SMEM>>>(h, wvh, bv, nullptr, nullptr, v, D_MODEL, D_MODEL);

    // 3) attention -> ctx (fp16)
    attn_kernel<<<dim3(SEQ / 64, BATCH * N_HEADS), 128, ATTN_SMEM>>>(q, k, v, ctx);

    // 4) W_O + residual -> x1 (fp32)
    gemm_h<2><<<g1024, 256, G_SMEM>>>(ctx, woh, bo, x, x1, nullptr, D_MODEL, D_MODEL);

    // 5) LN2 -> h (fp16)
    ln_kernel<<<TOK, 256>>>(x1, ln2a, ln2b, h);

    // 6) FFN
    gemm_h<1><<<dim3(D_FF / 128, TOK / 128), 256, G_SMEM>>>(h, w1h, b1, nullptr, nullptr, f1, D_FF, D_MODEL);
    gemm_h<2><<<g1024, 256, G_SMEM>>>(f1, w2h, b2, x1, out, nullptr, D_MODEL, D_FF);
}